// round 1
// baseline (speedup 1.0000x reference)
#include <cuda_runtime.h>

#define NB    32
#define NPTS  2048
#define KNN   16
#define NTOT  (NB * NPTS)
#define CH    32

// Scratch (device globals: no allocation allowed in kernel_launch)
__device__ int   g_idx[NTOT * KNN];   // global neighbor indices
__device__ float g_S[NTOT * CH];      // per-node source term  S[j]
__device__ float g_R[NTOT * CH];      // per-node target term  R[i]
__device__ float g_H[NTOT * CH];      // hidden after conv1 + relu

// ---------------------------------------------------------------------------
// kNN: one thread per point, batch positions staged in smem, streaming
// insertion-sorted top-16 (ascending). Strict '<' keeps lowest index on ties,
// matching jax.lax.top_k tie-breaking. Self (d2=0) is included (loop=True).
// ---------------------------------------------------------------------------
__global__ void knn_kernel(const float* __restrict__ pos, int* __restrict__ idx_out) {
    __shared__ float sx[NPTS], sy[NPTS], sz[NPTS];
    const int b     = blockIdx.x >> 4;   // 16 blocks of 128 threads per batch
    const int chunk = blockIdx.x & 15;
    const int base  = b * NPTS;

    for (int t = threadIdx.x; t < NPTS; t += blockDim.x) {
        sx[t] = pos[(base + t) * 3 + 0];
        sy[t] = pos[(base + t) * 3 + 1];
        sz[t] = pos[(base + t) * 3 + 2];
    }
    __syncthreads();

    const int   li = chunk * 128 + threadIdx.x;       // 0..2047
    const float xi = sx[li], yi = sy[li], zi = sz[li];

    float bd[KNN];
    int   bi[KNN];
#pragma unroll
    for (int q = 0; q < KNN; ++q) { bd[q] = 3.4e38f; bi[q] = 0; }

    for (int j = 0; j < NPTS; ++j) {
        float dx = sx[j] - xi;
        float dy = sy[j] - yi;
        float dz = sz[j] - zi;
        float d2 = dx * dx + dy * dy + dz * dz;
        if (d2 < bd[KNN - 1]) {
            float v = d2; int vi = j;
#pragma unroll
            for (int q = 0; q < KNN; ++q) {
                bool lt = (v < bd[q]);
                float tv = bd[q]; int ti = bi[q];
                if (lt) { bd[q] = v; bi[q] = vi; v = tv; vi = ti; }
            }
        }
    }

    const int gi = base + li;
#pragma unroll
    for (int q = 0; q < KNN; ++q)
        idx_out[gi * KNN + q] = base + bi[q];
}

// ---------------------------------------------------------------------------
// Prep for layer 1 (h == p):
//   pre(i,j) = p_j@(Wh+Wr) - p_i@Wr + b1a  =>  S[j] = p_j@(Wh+Wr), R[i] = p_i@Wr
// w1a is [6,32] row-major: rows 0..2 multiply h_j(=p_j), rows 3..5 multiply rel.
// One thread per (node, channel).
// ---------------------------------------------------------------------------
__global__ void prep1_kernel(const float* __restrict__ pos,
                             const float* __restrict__ w1a,
                             float* __restrict__ S, float* __restrict__ R) {
    int t = blockIdx.x * blockDim.x + threadIdx.x;   // NTOT*32 threads
    int node = t >> 5;
    int c    = t & 31;
    float x = pos[node * 3 + 0];
    float y = pos[node * 3 + 1];
    float z = pos[node * 3 + 2];
    float wr0 = w1a[3 * 32 + c], wr1 = w1a[4 * 32 + c], wr2 = w1a[5 * 32 + c];
    float wh0 = w1a[0 * 32 + c] + wr0;
    float wh1 = w1a[1 * 32 + c] + wr1;
    float wh2 = w1a[2 * 32 + c] + wr2;
    S[t] = x * wh0 + y * wh1 + z * wh2;
    R[t] = x * wr0 + y * wr1 + z * wr2;
}

// ---------------------------------------------------------------------------
// Prep for layer 2:
//   S[j] = h_j @ w2a[0:32] + p_j @ w2a[32:35];   R[i] = p_i @ w2a[32:35]
// Warp per node; H row distributed one value per lane, broadcast via shfl.
// ---------------------------------------------------------------------------
__global__ void prep2_kernel(const float* __restrict__ pos,
                             const float* __restrict__ H,
                             const float* __restrict__ w2a,
                             float* __restrict__ S, float* __restrict__ R) {
    const int lane = threadIdx.x & 31;
    const int wid  = threadIdx.x >> 5;
    const int wpb  = blockDim.x >> 5;

    float wa[CH];
#pragma unroll
    for (int d = 0; d < CH; ++d) wa[d] = w2a[d * 32 + lane];
    const float wr0 = w2a[(32 + 0) * 32 + lane];
    const float wr1 = w2a[(32 + 1) * 32 + lane];
    const float wr2 = w2a[(32 + 2) * 32 + lane];

    for (int node = blockIdx.x * wpb + wid; node < NTOT; node += gridDim.x * wpb) {
        float x = pos[node * 3 + 0];
        float y = pos[node * 3 + 1];
        float z = pos[node * 3 + 2];
        float r = x * wr0 + y * wr1 + z * wr2;
        float h = H[node * 32 + lane];
        float acc = r;
#pragma unroll
        for (int d = 0; d < CH; ++d) {
            float hd = __shfl_sync(0xffffffffu, h, d);
            acc = fmaf(hd, wa[d], acc);
        }
        S[node * 32 + lane] = acc;
        R[node * 32 + lane] = r;
    }
}

// ---------------------------------------------------------------------------
// Edge MLP + max reduction. Warp per node:
//   e_k   = relu(S[j_k] - R[i] + ba)           (staged in smem, lane = channel)
//   m_k   = e_k @ wb                            (lane = out channel, wb col in regs)
//   out   = max_k m_k + bb   (optionally relu)
// ---------------------------------------------------------------------------
template <bool RELU_OUT>
__global__ void layer_kernel(const float* __restrict__ S,
                             const float* __restrict__ R,
                             const float* __restrict__ ba,
                             const float* __restrict__ wb,
                             const float* __restrict__ bb,
                             const int* __restrict__ idx,
                             float* __restrict__ out) {
    __shared__ __align__(16) float sE[8][KNN][CH];   // 8 warps/block
    const int lane = threadIdx.x & 31;
    const int wid  = threadIdx.x >> 5;
    const int wpb  = blockDim.x >> 5;

    float wcol[CH];
#pragma unroll
    for (int d = 0; d < CH; ++d) wcol[d] = wb[d * 32 + lane];
    const float bav = ba[lane];
    const float bbv = bb[lane];

    for (int node = blockIdx.x * wpb + wid; node < NTOT; node += gridDim.x * wpb) {
        const float vb = bav - R[node * 32 + lane];
        const int myj  = idx[node * KNN + (lane & 15)];

#pragma unroll
        for (int k = 0; k < KNN; ++k) {
            int j = __shfl_sync(0xffffffffu, myj, k);
            float e = S[j * 32 + lane] + vb;
            sE[wid][k][lane] = fmaxf(e, 0.0f);
        }
        __syncwarp();

        float mx = -3.4e38f;
#pragma unroll
        for (int k = 0; k < KNN; ++k) {
            const float* ek = &sE[wid][k][0];
            float acc = 0.0f;
#pragma unroll
            for (int c = 0; c < CH; c += 4) {
                float4 ev = *reinterpret_cast<const float4*>(ek + c);
                acc = fmaf(ev.x, wcol[c + 0], acc);
                acc = fmaf(ev.y, wcol[c + 1], acc);
                acc = fmaf(ev.z, wcol[c + 2], acc);
                acc = fmaf(ev.w, wcol[c + 3], acc);
            }
            mx = fmaxf(mx, acc);
        }
        __syncwarp();

        float r = mx + bbv;
        if (RELU_OUT) r = fmaxf(r, 0.0f);
        out[node * 32 + lane] = r;
    }
}

// ---------------------------------------------------------------------------
// Launch. Inputs (metadata order):
//  0 pos [196608] f32, 1 batch [65536] i64 (implicit; unused),
//  2 w1a [6,32], 3 b1a [32], 4 w1b [32,32], 5 b1b [32],
//  6 w2a [35,32], 7 b2a [32], 8 w2b [32,32], 9 b2b [32]
// Output: [65536, 32] f32.
// ---------------------------------------------------------------------------
extern "C" void kernel_launch(void* const* d_in, const int* in_sizes, int n_in,
                              void* d_out, int out_size) {
    const float* pos = (const float*)d_in[0];
    const float* w1a = (const float*)d_in[2];
    const float* b1a = (const float*)d_in[3];
    const float* w1b = (const float*)d_in[4];
    const float* b1b = (const float*)d_in[5];
    const float* w2a = (const float*)d_in[6];
    const float* b2a = (const float*)d_in[7];
    const float* w2b = (const float*)d_in[8];
    const float* b2b = (const float*)d_in[9];
    float* out = (float*)d_out;

    int*   idx; cudaGetSymbolAddress((void**)&idx, g_idx);
    float* S;   cudaGetSymbolAddress((void**)&S,   g_S);
    float* R;   cudaGetSymbolAddress((void**)&R,   g_R);
    float* H;   cudaGetSymbolAddress((void**)&H,   g_H);

    // 1. kNN graph
    knn_kernel<<<NB * 16, 128>>>(pos, idx);

    // 2. conv1
    prep1_kernel<<<(NTOT * CH) / 256, 256>>>(pos, w1a, S, R);
    layer_kernel<true><<<1024, 256>>>(S, R, b1a, w1b, b1b, idx, H);

    // 3. conv2
    prep2_kernel<<<1024, 256>>>(pos, H, w2a, S, R);
    layer_kernel<false><<<1024, 256>>>(S, R, b2a, w2b, b2b, idx, out);
}

// round 3
// speedup vs baseline: 1.4445x; 1.4445x over previous
#include <cuda_runtime.h>
#include <cstdint>

#define NB    32
#define NPTS  2048
#define KNN   16
#define NTOT  (NB * NPTS)
#define CH    32
#define BUFC  24   // per-thread candidate buffer slots (16 + tie/guard slack)

// Scratch (device globals: no allocation allowed in kernel_launch)
__device__ int   g_idx[NTOT * KNN];
__device__ float g_S[NTOT * CH];
__device__ float g_R[NTOT * CH];
__device__ float g_H[NTOT * CH];

// ---------------------------------------------------------------------------
// packed f32x2 helpers (Blackwell)
// ---------------------------------------------------------------------------
__device__ __forceinline__ unsigned long long ffma2(unsigned long long a,
                                                    unsigned long long b,
                                                    unsigned long long c) {
    unsigned long long d;
    asm("fma.rn.f32x2 %0, %1, %2, %3;" : "=l"(d) : "l"(a), "l"(b), "l"(c));
    return d;
}
__device__ __forceinline__ unsigned long long fadd2(unsigned long long a,
                                                    unsigned long long b) {
    unsigned long long d;
    asm("add.rn.f32x2 %0, %1, %2;" : "=l"(d) : "l"(a), "l"(b));
    return d;
}
__device__ __forceinline__ unsigned long long pack2(float lo, float hi) {
    unsigned long long d;
    asm("mov.b64 %0, {%1, %2};" : "=l"(d) : "f"(lo), "f"(hi));
    return d;
}
__device__ __forceinline__ void unpack2(unsigned long long v, float& lo, float& hi) {
    asm("mov.b64 {%0, %1}, %2;" : "=f"(lo), "=f"(hi) : "l"(v));
}

// ---------------------------------------------------------------------------
// compare-exchange helpers. Keys are nonnegative fp32 distances, so unsigned
// bit compare == IEEE compare. ce_u rides the ALU pipe (IMNMX), ce_f the FMA
// pipe (FMNMX) — mixed deliberately to balance issue across both pipes.
// ---------------------------------------------------------------------------
__device__ __forceinline__ void ce_u(float& a, float& b) {
    unsigned x = __float_as_uint(a), y = __float_as_uint(b);
    a = __uint_as_float(min(x, y));
    b = __uint_as_float(max(x, y));
}
__device__ __forceinline__ void ce_f(float& a, float& b) {
    float lo = fminf(a, b), hi = fmaxf(a, b);
    a = lo; b = hi;
}
__device__ __forceinline__ void ce64(unsigned long long& a, unsigned long long& b) {
    unsigned long long x = a, y = b;
    bool sw = (y < x);
    a = sw ? y : x;
    b = sw ? x : y;
}
__device__ __forceinline__ float dist2(float4 p, float xi, float yi, float zi) {
    float dx = p.x - xi, dy = p.y - yi, dz = p.z - zi;
    return fmaf(dz, dz, fmaf(dy, dy, dx * dx));
}

// ---------------------------------------------------------------------------
// kNN, exact, 3 phases, one thread per point:
//  A) branch-free streaming top-16 on EXACT d2 bits (no payload) -> tau
//  B) rescan, append j with d2 <= tau(+8ulp) to smem buffer (~16 appends)
//  C) exact u64 (d2_bits, j) bitonic-32 over <=24 candidates -> top-16 set
//     with lowest-index tie-break, matching jax.lax.top_k.
// ---------------------------------------------------------------------------
__global__ void knn_kernel(const float* __restrict__ pos, int* __restrict__ idx_out) {
    __shared__ float4   sp[NPTS];          // 32 KB
    __shared__ unsigned sbuf[128][BUFC + 1];  // stride 25 words: conflict-free

    const int b     = blockIdx.x >> 4;     // 16 blocks of 128 threads per batch
    const int chunk = blockIdx.x & 15;
    const int base  = b * NPTS;
    const int tid   = threadIdx.x;

    for (int t = tid; t < NPTS; t += blockDim.x) {
        const float* p = pos + (base + t) * 3;
        sp[t] = make_float4(p[0], p[1], p[2], 0.0f);
    }
    __syncthreads();

    const int    li = chunk * 128 + tid;
    const float4 pi = sp[li];
    const float  xi = pi.x, yi = pi.y, zi = pi.z;
    const float  FINF = __uint_as_float(0x7F800000u);

    // ---- Pass A: exact threshold via bitonic tile-merge (d2-only keys) ----
    float best[KNN];
#pragma unroll
    for (int q = 0; q < KNN; ++q) best[q] = FINF;

#pragma unroll 1
    for (int tile = 0; tile < NPTS / 16; ++tile) {
        float key[16];
#pragma unroll
        for (int u = 0; u < 16; ++u)
            key[u] = dist2(sp[tile * 16 + u], xi, yi, zi);

        // bitonic sort 16 ascending (ALU pipe)
#pragma unroll
        for (int k = 2; k <= 16; k <<= 1) {
#pragma unroll
            for (int s = k >> 1; s > 0; s >>= 1) {
#pragma unroll
                for (int i = 0; i < 16; ++i) {
                    int l = i ^ s;
                    if (l > i) {
                        if ((i & k) == 0) ce_u(key[i], key[l]);
                        else              ce_u(key[l], key[i]);
                    }
                }
            }
        }
        // merge-fold lowest-16 (FMA pipe)
#pragma unroll
        for (int i = 0; i < 16; ++i) best[i] = fminf(best[i], key[15 - i]);
        // bitonic clean (FMA pipe)
#pragma unroll
        for (int s = 8; s > 0; s >>= 1) {
#pragma unroll
            for (int i = 0; i < 16; ++i) {
                int l = i ^ s;
                if (l > i) ce_f(best[i], best[l]);
            }
        }
    }
    const float tauf = __uint_as_float(__float_as_uint(best[KNN - 1]) + 8u);

    // ---- Pass B: collect candidate indices ----
    int cnt = 0;
#pragma unroll 8
    for (int j = 0; j < NPTS; ++j) {
        float d2 = dist2(sp[j], xi, yi, zi);
        if (d2 <= tauf && cnt < BUFC) {
            sbuf[tid][cnt] = (unsigned)j;
            ++cnt;
        }
    }

    // ---- Pass C: exact (d2, j) selection of 16 smallest ----
    unsigned long long arr[32];
#pragma unroll
    for (int u = 0; u < BUFC; ++u) {
        bool valid = (u < cnt);
        unsigned jj = valid ? sbuf[tid][u] : 0u;
        float d2 = dist2(sp[jj], xi, yi, zi);
        arr[u] = valid
            ? (((unsigned long long)__float_as_uint(d2) << 32) | jj)
            : 0xFFFFFFFFFFFFFFFFull;
    }
#pragma unroll
    for (int u = BUFC; u < 32; ++u) arr[u] = 0xFFFFFFFFFFFFFFFFull;

#pragma unroll
    for (int k = 2; k <= 32; k <<= 1) {
#pragma unroll
        for (int s = k >> 1; s > 0; s >>= 1) {
#pragma unroll
            for (int i = 0; i < 32; ++i) {
                int l = i ^ s;
                if (l > i) {
                    if ((i & k) == 0) ce64(arr[i], arr[l]);
                    else              ce64(arr[l], arr[i]);
                }
            }
        }
    }

    const int gi = base + li;
#pragma unroll
    for (int q = 0; q < KNN; ++q)
        idx_out[gi * KNN + q] = base + (int)(unsigned)(arr[q] & 0xFFFFFFFFull);
}

// ---------------------------------------------------------------------------
// Prep for layer 1 (h == p): S[j] = p_j@(Wh+Wr), R[i] = p_i@Wr
// ---------------------------------------------------------------------------
__global__ void prep1_kernel(const float* __restrict__ pos,
                             const float* __restrict__ w1a,
                             float* __restrict__ S, float* __restrict__ R) {
    int t = blockIdx.x * blockDim.x + threadIdx.x;
    int node = t >> 5;
    int c    = t & 31;
    float x = pos[node * 3 + 0];
    float y = pos[node * 3 + 1];
    float z = pos[node * 3 + 2];
    float wr0 = w1a[3 * 32 + c], wr1 = w1a[4 * 32 + c], wr2 = w1a[5 * 32 + c];
    float wh0 = w1a[0 * 32 + c] + wr0;
    float wh1 = w1a[1 * 32 + c] + wr1;
    float wh2 = w1a[2 * 32 + c] + wr2;
    S[t] = x * wh0 + y * wh1 + z * wh2;
    R[t] = x * wr0 + y * wr1 + z * wr2;
}

// ---------------------------------------------------------------------------
// Prep for layer 2: S[j] = h_j @ w2a[0:32] + p_j @ w2a[32:35]; R[i] = p_i @ Wr
// ---------------------------------------------------------------------------
__global__ void prep2_kernel(const float* __restrict__ pos,
                             const float* __restrict__ H,
                             const float* __restrict__ w2a,
                             float* __restrict__ S, float* __restrict__ R) {
    const int lane = threadIdx.x & 31;
    const int wid  = threadIdx.x >> 5;
    const int wpb  = blockDim.x >> 5;

    float wa[CH];
#pragma unroll
    for (int d = 0; d < CH; ++d) wa[d] = w2a[d * 32 + lane];
    const float wr0 = w2a[(32 + 0) * 32 + lane];
    const float wr1 = w2a[(32 + 1) * 32 + lane];
    const float wr2 = w2a[(32 + 2) * 32 + lane];

    for (int node = blockIdx.x * wpb + wid; node < NTOT; node += gridDim.x * wpb) {
        float x = pos[node * 3 + 0];
        float y = pos[node * 3 + 1];
        float z = pos[node * 3 + 2];
        float r = x * wr0 + y * wr1 + z * wr2;
        float h = H[node * 32 + lane];
        float acc = r;
#pragma unroll
        for (int d = 0; d < CH; ++d) {
            float hd = __shfl_sync(0xffffffffu, h, d);
            acc = fmaf(hd, wa[d], acc);
        }
        S[node * 32 + lane] = acc;
        R[node * 32 + lane] = r;
    }
}

// ---------------------------------------------------------------------------
// Edge MLP + max reduction. Warp per node; FFMA2 packed GEMV.
// ---------------------------------------------------------------------------
template <bool RELU_OUT>
__global__ void layer_kernel(const float* __restrict__ S,
                             const float* __restrict__ R,
                             const float* __restrict__ ba,
                             const float* __restrict__ wb,
                             const float* __restrict__ bb,
                             const int* __restrict__ idx,
                             float* __restrict__ out) {
    __shared__ __align__(16) float sE[8][KNN][CH];
    const int lane = threadIdx.x & 31;
    const int wid  = threadIdx.x >> 5;
    const int wpb  = blockDim.x >> 5;

    unsigned long long wp[CH / 2];
#pragma unroll
    for (int d = 0; d < CH / 2; ++d)
        wp[d] = pack2(wb[(2 * d) * 32 + lane], wb[(2 * d + 1) * 32 + lane]);
    const float bav = ba[lane];
    const float bbv = bb[lane];

    for (int node = blockIdx.x * wpb + wid; node < NTOT; node += gridDim.x * wpb) {
        const float vb = bav - R[node * 32 + lane];
        const int myj  = idx[node * KNN + (lane & 15)];

#pragma unroll
        for (int k = 0; k < KNN; ++k) {
            int j = __shfl_sync(0xffffffffu, myj, k);
            float e = S[j * 32 + lane] + vb;
            sE[wid][k][lane] = fmaxf(e, 0.0f);
        }
        __syncwarp();

        float mx = -3.4e38f;
#pragma unroll
        for (int k = 0; k < KNN; ++k) {
            const ulonglong2* ek = reinterpret_cast<const ulonglong2*>(&sE[wid][k][0]);
            unsigned long long a0 = 0, a1 = 0, a2 = 0, a3 = 0;
#pragma unroll
            for (int c = 0; c < 4; ++c) {
                ulonglong2 e2a = ek[2 * c + 0];
                ulonglong2 e2b = ek[2 * c + 1];
                a0 = ffma2(e2a.x, wp[4 * c + 0], a0);
                a1 = ffma2(e2a.y, wp[4 * c + 1], a1);
                a2 = ffma2(e2b.x, wp[4 * c + 2], a2);
                a3 = ffma2(e2b.y, wp[4 * c + 3], a3);
            }
            unsigned long long t = fadd2(fadd2(a0, a1), fadd2(a2, a3));
            float lo, hi;
            unpack2(t, lo, hi);
            mx = fmaxf(mx, lo + hi);
        }
        __syncwarp();

        float r = mx + bbv;
        if (RELU_OUT) r = fmaxf(r, 0.0f);
        out[node * 32 + lane] = r;
    }
}

// ---------------------------------------------------------------------------
extern "C" void kernel_launch(void* const* d_in, const int* in_sizes, int n_in,
                              void* d_out, int out_size) {
    const float* pos = (const float*)d_in[0];
    const float* w1a = (const float*)d_in[2];
    const float* b1a = (const float*)d_in[3];
    const float* w1b = (const float*)d_in[4];
    const float* b1b = (const float*)d_in[5];
    const float* w2a = (const float*)d_in[6];
    const float* b2a = (const float*)d_in[7];
    const float* w2b = (const float*)d_in[8];
    const float* b2b = (const float*)d_in[9];
    float* out = (float*)d_out;

    int*   idx; cudaGetSymbolAddress((void**)&idx, g_idx);
    float* S;   cudaGetSymbolAddress((void**)&S,   g_S);
    float* R;   cudaGetSymbolAddress((void**)&R,   g_R);
    float* H;   cudaGetSymbolAddress((void**)&H,   g_H);

    // 1. kNN graph
    knn_kernel<<<NB * 16, 128>>>(pos, idx);

    // 2. conv1
    prep1_kernel<<<(NTOT * CH) / 256, 256>>>(pos, w1a, S, R);
    layer_kernel<true><<<1024, 256>>>(S, R, b1a, w1b, b1b, idx, H);

    // 3. conv2
    prep2_kernel<<<1024, 256>>>(pos, H, w2a, S, R);
    layer_kernel<false><<<1024, 256>>>(S, R, b2a, w2b, b2b, idx, out);
}

// round 5
// speedup vs baseline: 1.6050x; 1.1111x over previous
#include <cuda_runtime.h>
#include <cstdint>

#define NB    32
#define NPTS  2048
#define KNN   16
#define NTOT  (NB * NPTS)
#define CH    32
#define HALF  1024           // candidates per half
#define PPB   64             // points per block (x2 halves = 128 threads)

// Scratch (device globals: no allocation allowed in kernel_launch)
__device__ int   g_idx[NTOT * KNN];
__device__ float g_S[NTOT * CH];
__device__ float g_R[NTOT * CH];
__device__ float g_H[NTOT * CH];

typedef unsigned long long u64;

// ---------------------------------------------------------------------------
// packed f32x2 helpers (layer kernel only; these compiled fine in round 3)
// ---------------------------------------------------------------------------
__device__ __forceinline__ u64 ffma2(u64 a, u64 b, u64 c) {
    u64 d; asm("fma.rn.f32x2 %0, %1, %2, %3;" : "=l"(d) : "l"(a), "l"(b), "l"(c)); return d;
}
__device__ __forceinline__ u64 fadd2(u64 a, u64 b) {
    u64 d; asm("add.rn.f32x2 %0, %1, %2;" : "=l"(d) : "l"(a), "l"(b)); return d;
}
__device__ __forceinline__ u64 pack2(float lo, float hi) {
    u64 d; asm("mov.b64 %0, {%1, %2};" : "=l"(d) : "f"(lo), "f"(hi)); return d;
}
__device__ __forceinline__ void unpack2(u64 v, float& lo, float& hi) {
    asm("mov.b64 {%0, %1}, %2;" : "=f"(lo), "=f"(hi) : "l"(v));
}

// ---------------------------------------------------------------------------
// compare-exchange helpers (scalar; alu/fma pipe split as in round 3)
// ---------------------------------------------------------------------------
__device__ __forceinline__ void ce_u(float& a, float& b) {
    unsigned x = __float_as_uint(a), y = __float_as_uint(b);
    a = __uint_as_float(min(x, y));
    b = __uint_as_float(max(x, y));
}
__device__ __forceinline__ void ce_f(float& a, float& b) {
    float lo = fminf(a, b), hi = fmaxf(a, b);
    a = lo; b = hi;
}
__device__ __forceinline__ void ce64(u64& a, u64& b) {
    u64 x = a, y = b;
    bool sw = (y < x);
    a = sw ? y : x;
    b = sw ? x : y;
}
__device__ __forceinline__ float dist2s(float x, float y, float z,
                                        float xi, float yi, float zi) {
    float dx = x - xi, dy = y - yi, dz = z - zi;
    return fmaf(dz, dz, fmaf(dy, dy, dx * dx));
}

// ---------------------------------------------------------------------------
// kNN, exact. Block = 64 points x 2 candidate-halves (128 threads).
//  A) per (point,half): bitonic tile-merge streaming top-16 on exact d2
//  B) tau = exact 16th of union (fold identity), collect j with d2<=tau(+8ulp)
//  C) exact u64 (d2,j) bitonic-32 over <=32 candidates -> top-16 set,
//     low-index tie-break (matches jax.lax.top_k)
// ---------------------------------------------------------------------------
__global__ void knn_kernel(const float* __restrict__ pos, int* __restrict__ idx_out) {
    __shared__ float2   sxy[NPTS];                 // 16 KB
    __shared__ float    sz[NPTS];                  // 8 KB
    __shared__ unsigned scomb[PPB * 32];           // 8 KB; also holds best16 floats

    const int b     = blockIdx.x >> 5;             // 32 blocks of 64 points per batch
    const int chunk = blockIdx.x & 31;
    const int base  = b * NPTS;
    const int tid   = threadIdx.x;
    const int half  = tid >> 6;                    // 0 or 1
    const int lp    = tid & 63;                    // local point 0..63
    const int li    = chunk * PPB + lp;            // point index within batch
    const int j0    = half * HALF;

    for (int t = tid; t < NPTS; t += blockDim.x) {
        const float* p = pos + (base + t) * 3;
        sxy[t] = make_float2(p[0], p[1]);
        sz[t]  = p[2];
    }
    __syncthreads();

    const float xi = sxy[li].x, yi = sxy[li].y, zi = sz[li];
    const float FINF = __uint_as_float(0x7F800000u);

    // ---- Pass A: exact streaming top-16 over this thread's half ----
    float best[KNN];
#pragma unroll
    for (int q = 0; q < KNN; ++q) best[q] = FINF;

#pragma unroll 1
    for (int tile = 0; tile < HALF / 16; ++tile) {
        float key[16];
#pragma unroll
        for (int u = 0; u < 16; ++u) {
            int j = j0 + tile * 16 + u;
            float2 xy = sxy[j];
            key[u] = dist2s(xy.x, xy.y, sz[j], xi, yi, zi);
        }
        // bitonic sort 16 ascending (ALU pipe)
#pragma unroll
        for (int k = 2; k <= 16; k <<= 1) {
#pragma unroll
            for (int s = k >> 1; s > 0; s >>= 1) {
#pragma unroll
                for (int i = 0; i < 16; ++i) {
                    int l = i ^ s;
                    if (l > i) {
                        if ((i & k) == 0) ce_u(key[i], key[l]);
                        else              ce_u(key[l], key[i]);
                    }
                }
            }
        }
        // merge-fold lowest-16 (FMA pipe)
#pragma unroll
        for (int i = 0; i < 16; ++i) best[i] = fminf(best[i], key[15 - i]);
        // bitonic clean (FMA pipe)
#pragma unroll
        for (int s = 8; s > 0; s >>= 1) {
#pragma unroll
            for (int i = 0; i < 16; ++i) {
                int l = i ^ s;
                if (l > i) ce_f(best[i], best[l]);
            }
        }
    }

    // ---- publish best16, compute exact tau of the union ----
    float* sbest = reinterpret_cast<float*>(scomb);   // [128][16]
#pragma unroll
    for (int q = 0; q < KNN; ++q) sbest[tid * KNN + q] = best[q];
    __syncthreads();

    float tau_raw = -FINF;
#pragma unroll
    for (int i = 0; i < KNN; ++i) {
        float a = sbest[lp * KNN + i];
        float c = sbest[(lp + 64) * KNN + (KNN - 1 - i)];
        tau_raw = fmaxf(tau_raw, fminf(a, c));
    }
    const float tauf = __uint_as_float(__float_as_uint(tau_raw) + 8u);
    __syncthreads();

    // ---- reinit scomb as candidate slots ----
    for (int u = tid; u < PPB * 32; u += blockDim.x) scomb[u] = 0xFFFFFFFFu;
    __syncthreads();

    // ---- Pass B: collect candidates from this half ----
    int cnt = 0;
#pragma unroll 8
    for (int j = j0; j < j0 + HALF; ++j) {
        float2 xy = sxy[j];
        float d2 = dist2s(xy.x, xy.y, sz[j], xi, yi, zi);
        if (d2 <= tauf && cnt < 16) {
            scomb[lp * 32 + half * 16 + cnt] = (unsigned)j;
            ++cnt;
        }
    }
    __syncthreads();

    // ---- Pass C: exact (d2, j) selection of 16 smallest (half-0 threads) ----
    if (half == 0) {
        u64 arr[32];
#pragma unroll
        for (int u = 0; u < 32; ++u) {
            unsigned jj = scomb[lp * 32 + u];
            if (jj != 0xFFFFFFFFu) {
                float2 xy = sxy[jj];
                float d2 = dist2s(xy.x, xy.y, sz[jj], xi, yi, zi);
                arr[u] = ((u64)__float_as_uint(d2) << 32) | jj;
            } else {
                arr[u] = 0xFFFFFFFFFFFFFFFFull;
            }
        }
#pragma unroll
        for (int k = 2; k <= 32; k <<= 1) {
#pragma unroll
            for (int s = k >> 1; s > 0; s >>= 1) {
#pragma unroll
                for (int i = 0; i < 32; ++i) {
                    int l = i ^ s;
                    if (l > i) {
                        if ((i & k) == 0) ce64(arr[i], arr[l]);
                        else              ce64(arr[l], arr[i]);
                    }
                }
            }
        }
        const int gi = base + li;
#pragma unroll
        for (int q = 0; q < KNN; ++q)
            idx_out[gi * KNN + q] = base + (int)(unsigned)(arr[q] & 0xFFFFFFFFull);
    }
}

// ---------------------------------------------------------------------------
// Prep for layer 1 (h == p): S[j] = p_j@(Wh+Wr), R[i] = p_i@Wr
// ---------------------------------------------------------------------------
__global__ void prep1_kernel(const float* __restrict__ pos,
                             const float* __restrict__ w1a,
                             float* __restrict__ S, float* __restrict__ R) {
    int t = blockIdx.x * blockDim.x + threadIdx.x;
    int node = t >> 5;
    int c    = t & 31;
    float x = pos[node * 3 + 0];
    float y = pos[node * 3 + 1];
    float z = pos[node * 3 + 2];
    float wr0 = w1a[3 * 32 + c], wr1 = w1a[4 * 32 + c], wr2 = w1a[5 * 32 + c];
    float wh0 = w1a[0 * 32 + c] + wr0;
    float wh1 = w1a[1 * 32 + c] + wr1;
    float wh2 = w1a[2 * 32 + c] + wr2;
    S[t] = x * wh0 + y * wh1 + z * wh2;
    R[t] = x * wr0 + y * wr1 + z * wr2;
}

// ---------------------------------------------------------------------------
// Prep for layer 2: S[j] = h_j @ w2a[0:32] + p_j @ w2a[32:35]; R[i] = p_i @ Wr
// ---------------------------------------------------------------------------
__global__ void prep2_kernel(const float* __restrict__ pos,
                             const float* __restrict__ H,
                             const float* __restrict__ w2a,
                             float* __restrict__ S, float* __restrict__ R) {
    const int lane = threadIdx.x & 31;
    const int wid  = threadIdx.x >> 5;
    const int wpb  = blockDim.x >> 5;

    float wa[CH];
#pragma unroll
    for (int d = 0; d < CH; ++d) wa[d] = w2a[d * 32 + lane];
    const float wr0 = w2a[(32 + 0) * 32 + lane];
    const float wr1 = w2a[(32 + 1) * 32 + lane];
    const float wr2 = w2a[(32 + 2) * 32 + lane];

    for (int node = blockIdx.x * wpb + wid; node < NTOT; node += gridDim.x * wpb) {
        float x = pos[node * 3 + 0];
        float y = pos[node * 3 + 1];
        float z = pos[node * 3 + 2];
        float r = x * wr0 + y * wr1 + z * wr2;
        float h = H[node * 32 + lane];
        float acc = r;
#pragma unroll
        for (int d = 0; d < CH; ++d) {
            float hd = __shfl_sync(0xffffffffu, h, d);
            acc = fmaf(hd, wa[d], acc);
        }
        S[node * 32 + lane] = acc;
        R[node * 32 + lane] = r;
    }
}

// ---------------------------------------------------------------------------
// Edge MLP + max reduction. Warp per node; FFMA2 packed GEMV.
// ---------------------------------------------------------------------------
template <bool RELU_OUT>
__global__ void layer_kernel(const float* __restrict__ S,
                             const float* __restrict__ R,
                             const float* __restrict__ ba,
                             const float* __restrict__ wb,
                             const float* __restrict__ bb,
                             const int* __restrict__ idx,
                             float* __restrict__ out) {
    __shared__ __align__(16) float sE[8][KNN][CH];
    const int lane = threadIdx.x & 31;
    const int wid  = threadIdx.x >> 5;
    const int wpb  = blockDim.x >> 5;

    u64 wp[CH / 2];
#pragma unroll
    for (int d = 0; d < CH / 2; ++d)
        wp[d] = pack2(wb[(2 * d) * 32 + lane], wb[(2 * d + 1) * 32 + lane]);
    const float bav = ba[lane];
    const float bbv = bb[lane];

    for (int node = blockIdx.x * wpb + wid; node < NTOT; node += gridDim.x * wpb) {
        const float vb = bav - R[node * 32 + lane];
        const int myj  = idx[node * KNN + (lane & 15)];

#pragma unroll
        for (int k = 0; k < KNN; ++k) {
            int j = __shfl_sync(0xffffffffu, myj, k);
            float e = S[j * 32 + lane] + vb;
            sE[wid][k][lane] = fmaxf(e, 0.0f);
        }
        __syncwarp();

        float mx = -3.4e38f;
#pragma unroll
        for (int k = 0; k < KNN; ++k) {
            const ulonglong2* ek = reinterpret_cast<const ulonglong2*>(&sE[wid][k][0]);
            u64 a0 = 0, a1 = 0, a2 = 0, a3 = 0;
#pragma unroll
            for (int c = 0; c < 4; ++c) {
                ulonglong2 e2a = ek[2 * c + 0];
                ulonglong2 e2b = ek[2 * c + 1];
                a0 = ffma2(e2a.x, wp[4 * c + 0], a0);
                a1 = ffma2(e2a.y, wp[4 * c + 1], a1);
                a2 = ffma2(e2b.x, wp[4 * c + 2], a2);
                a3 = ffma2(e2b.y, wp[4 * c + 3], a3);
            }
            u64 t = fadd2(fadd2(a0, a1), fadd2(a2, a3));
            float lo, hi;
            unpack2(t, lo, hi);
            mx = fmaxf(mx, lo + hi);
        }
        __syncwarp();

        float r = mx + bbv;
        if (RELU_OUT) r = fmaxf(r, 0.0f);
        out[node * 32 + lane] = r;
    }
}

// ---------------------------------------------------------------------------
extern "C" void kernel_launch(void* const* d_in, const int* in_sizes, int n_in,
                              void* d_out, int out_size) {
    const float* pos = (const float*)d_in[0];
    const float* w1a = (const float*)d_in[2];
    const float* b1a = (const float*)d_in[3];
    const float* w1b = (const float*)d_in[4];
    const float* b1b = (const float*)d_in[5];
    const float* w2a = (const float*)d_in[6];
    const float* b2a = (const float*)d_in[7];
    const float* w2b = (const float*)d_in[8];
    const float* b2b = (const float*)d_in[9];
    float* out = (float*)d_out;

    int*   idx; cudaGetSymbolAddress((void**)&idx, g_idx);
    float* S;   cudaGetSymbolAddress((void**)&S,   g_S);
    float* R;   cudaGetSymbolAddress((void**)&R,   g_R);
    float* H;   cudaGetSymbolAddress((void**)&H,   g_H);

    // 1. kNN graph (1024 blocks: 32 batches x 32 point-chunks, 2 halves/point)
    knn_kernel<<<NB * 32, 128>>>(pos, idx);

    // 2. conv1
    prep1_kernel<<<(NTOT * CH) / 256, 256>>>(pos, w1a, S, R);
    layer_kernel<true><<<1024, 256>>>(S, R, b1a, w1b, b1b, idx, H);

    // 3. conv2
    prep2_kernel<<<1024, 256>>>(pos, H, w2a, S, R);
    layer_kernel<false><<<1024, 256>>>(S, R, b2a, w2b, b2b, idx, out);
}

// round 6
// speedup vs baseline: 1.8710x; 1.1658x over previous
#include <cuda_runtime.h>
#include <cuda_fp16.h>
#include <cstdint>

#define NB    32
#define NPTS  2048
#define KNN   16
#define NTOT  (NB * NPTS)
#define CH    32
#define HALF  1024           // candidates per half
#define PPB   64             // points per block (x2 halves = 128 threads)
#define SLOT  24             // candidate slots per half

// Scratch (device globals: no allocation allowed in kernel_launch)
__device__ int   g_idx[NTOT * KNN];
__device__ float g_S[NTOT * CH];
__device__ float g_R[NTOT * CH];
__device__ float g_H[NTOT * CH];

typedef unsigned long long u64;
typedef unsigned int u32;

// ---------------------------------------------------------------------------
// packed f32x2 helpers (Blackwell sm_103a): add/mul/fma only (no min/max!)
// ---------------------------------------------------------------------------
__device__ __forceinline__ u64 ffma2(u64 a, u64 b, u64 c) {
    u64 d; asm("fma.rn.f32x2 %0, %1, %2, %3;" : "=l"(d) : "l"(a), "l"(b), "l"(c)); return d;
}
__device__ __forceinline__ u64 fmul2(u64 a, u64 b) {
    u64 d; asm("mul.rn.f32x2 %0, %1, %2;" : "=l"(d) : "l"(a), "l"(b)); return d;
}
__device__ __forceinline__ u64 fadd2(u64 a, u64 b) {
    u64 d; asm("add.rn.f32x2 %0, %1, %2;" : "=l"(d) : "l"(a), "l"(b)); return d;
}
__device__ __forceinline__ u64 pack2(float lo, float hi) {
    u64 d; asm("mov.b64 %0, {%1, %2};" : "=l"(d) : "f"(lo), "f"(hi)); return d;
}
__device__ __forceinline__ void unpack2(u64 v, float& lo, float& hi) {
    asm("mov.b64 {%0, %1}, %2;" : "=f"(lo), "=f"(hi) : "l"(v));
}

// ---------------------------------------------------------------------------
// compare-exchange helpers
// ---------------------------------------------------------------------------
__device__ __forceinline__ void ce2h(__half2& a, __half2& b) {   // packed f16x2 CE
    __half2 lo = __hmin2(a, b), hi = __hmax2(a, b);
    a = lo; b = hi;
}
__device__ __forceinline__ void ceu(u32& a, u32& b) {            // u32 CE (ALU pipe)
    u32 lo = min(a, b), hi = max(a, b);
    a = lo; b = hi;
}
__device__ __forceinline__ void ce64(u64& a, u64& b) {
    u64 x = a, y = b;
    bool sw = (y < x);
    a = sw ? y : x;
    b = sw ? x : y;
}
// Scalar distance — bitwise-identical to the packed sequence:
// dx = x + (-xi); d2 = fma(dz,dz, fma(dy,dy, dx*dx))
__device__ __forceinline__ float dist2s(float x, float y, float z,
                                        float xi, float yi, float zi) {
    float dx = x - xi, dy = y - yi, dz = z - zi;
    return fmaf(dz, dz, fmaf(dy, dy, dx * dx));
}

// ---------------------------------------------------------------------------
// kNN, exact. Block = 64 points x 2 candidate-halves (128 threads).
//  A) f16x2 dual-stream bitonic tile-merge -> per-thread sorted-16 f16 keys;
//     kappa = exact 16th-smallest f16 key of the union (fold identity).
//     Monotone quantization => kappa == f16(tau_true); collecting
//     d2 <= bucket_upper_edge(kappa) provably includes the true top-16.
//  B) packed-f32 rescan, append hits to per-half slots (<=24, safe).
//  C) exact u64 (f32 d2-bits, j) per-half bitonic-32 + 16x16 merge ->
//     exact top-16, low-index tie-break (matches jax.lax.top_k).
// ---------------------------------------------------------------------------
__global__ void knn_kernel(const float* __restrict__ pos, int* __restrict__ idx_out) {
    __shared__ __align__(16) float sx[NPTS], sy[NPTS], sz[NPTS];   // 24 KB
    __shared__ __align__(16) u32   scomb[PPB * 48];                // 12 KB (aliased)

    const int b     = blockIdx.x >> 5;          // 32 blocks of 64 points per batch
    const int chunk = blockIdx.x & 31;
    const int base  = b * NPTS;
    const int tid   = threadIdx.x;
    const int half  = tid >> 6;                 // 0 or 1
    const int lp    = tid & 63;                 // local point 0..63
    const int li    = chunk * PPB + lp;
    const int j0    = half * HALF;

    for (int t = tid; t < NPTS; t += blockDim.x) {
        const float* p = pos + (base + t) * 3;
        sx[t] = p[0]; sy[t] = p[1]; sz[t] = p[2];
    }
    __syncthreads();

    const float xi = sx[li], yi = sy[li], zi = sz[li];
    const u64 nxi2 = pack2(-xi, -xi);
    const u64 nyi2 = pack2(-yi, -yi);
    const u64 nzi2 = pack2(-zi, -zi);

    // ---- Pass A: f16x2 dual-stream streaming top-16 over this half ----
    const __half2 HINF2 = __halves2half2(__ushort_as_half(0x7C00),
                                         __ushort_as_half(0x7C00));
    __half2 best2[KNN];
#pragma unroll
    for (int q = 0; q < KNN; ++q) best2[q] = HINF2;

#pragma unroll 1
    for (int tile = 0; tile < HALF / 32; ++tile) {   // 32 candidates / tile
        __half2 key[16];
#pragma unroll
        for (int u = 0; u < 16; ++u) {
            int j = j0 + tile * 32 + 2 * u;          // pair (j, j+1)
            u64 x2 = *reinterpret_cast<const u64*>(&sx[j]);
            u64 y2 = *reinterpret_cast<const u64*>(&sy[j]);
            u64 z2 = *reinterpret_cast<const u64*>(&sz[j]);
            u64 dx2 = fadd2(x2, nxi2);
            u64 dy2 = fadd2(y2, nyi2);
            u64 dz2 = fadd2(z2, nzi2);
            u64 d2p = ffma2(dz2, dz2, ffma2(dy2, dy2, fmul2(dx2, dx2)));
            float dlo, dhi;
            unpack2(d2p, dlo, dhi);
            key[u] = __floats2half2_rn(dlo, dhi);    // lo half = even j stream
        }
        // bitonic sort 16 ascending — both f16 streams at once
#pragma unroll
        for (int k = 2; k <= 16; k <<= 1) {
#pragma unroll
            for (int s = k >> 1; s > 0; s >>= 1) {
#pragma unroll
                for (int i = 0; i < 16; ++i) {
                    int l = i ^ s;
                    if (l > i) {
                        if ((i & k) == 0) ce2h(key[i], key[l]);
                        else              ce2h(key[l], key[i]);
                    }
                }
            }
        }
        // merge-fold lowest-16 per stream
#pragma unroll
        for (int i = 0; i < 16; ++i) best2[i] = __hmin2(best2[i], key[15 - i]);
        // bitonic clean
#pragma unroll
        for (int s = 8; s > 0; s >>= 1) {
#pragma unroll
            for (int i = 0; i < 16; ++i) {
                int l = i ^ s;
                if (l > i) ce2h(best2[i], best2[l]);
            }
        }
    }

    // intra-thread merge of lo/hi streams (u32 compares on f16 bits; ALU pipe)
    u32 lo16[KNN], hi16[KNN];
#pragma unroll
    for (int i = 0; i < KNN; ++i) {
        lo16[i] = (u32)__half_as_ushort(__low2half(best2[i]));
        hi16[i] = (u32)__half_as_ushort(__high2half(best2[i]));
    }
#pragma unroll
    for (int i = 0; i < KNN; ++i) lo16[i] = min(lo16[i], hi16[KNN - 1 - i]);
#pragma unroll
    for (int s = 8; s > 0; s >>= 1) {
#pragma unroll
        for (int i = 0; i < KNN; ++i) {
            int l = i ^ s;
            if (l > i) ceu(lo16[i], lo16[l]);
        }
    }

    // publish per-thread sorted-16 key list; kappa = 16th of the 2-thread union
    u32* sbest = scomb;                              // [128][16]
#pragma unroll
    for (int q = 0; q < KNN; ++q) sbest[tid * KNN + q] = lo16[q];
    __syncthreads();

    u32 kap = 0;
#pragma unroll
    for (int i = 0; i < KNN; ++i)
        kap = max(kap, min(sbest[lp * KNN + i], sbest[(lp + 64) * KNN + (KNN - 1 - i)]));
    // f32 collect bound = upper edge of kappa's rn-bucket (+ margin)
    const float fk = __half2float(__ushort_as_half((unsigned short)kap));
    const float Bf = fmaf(fk, 4.8828125e-4f, fk) + 6e-8f;   // fk*(1+2^-11)+eps
    __syncthreads();

    // reinit scomb as candidate slots
    for (int u = tid; u < PPB * 48; u += blockDim.x) scomb[u] = 0xFFFFFFFFu;
    __syncthreads();

    // ---- Pass B: collect candidates from this half (packed distances) ----
    int cnt = 0;
    const int sb0 = lp * 48 + half * SLOT;
#pragma unroll 4
    for (int j = j0; j < j0 + HALF; j += 2) {
        u64 x2 = *reinterpret_cast<const u64*>(&sx[j]);
        u64 y2 = *reinterpret_cast<const u64*>(&sy[j]);
        u64 z2 = *reinterpret_cast<const u64*>(&sz[j]);
        u64 dx2 = fadd2(x2, nxi2);
        u64 dy2 = fadd2(y2, nyi2);
        u64 dz2 = fadd2(z2, nzi2);
        u64 d2p = ffma2(dz2, dz2, ffma2(dy2, dy2, fmul2(dx2, dx2)));
        float dlo, dhi;
        unpack2(d2p, dlo, dhi);
        if (dlo <= Bf && cnt < SLOT) { scomb[sb0 + cnt] = (u32)j;       ++cnt; }
        if (dhi <= Bf && cnt < SLOT) { scomb[sb0 + cnt] = (u32)(j + 1); ++cnt; }
    }
    __syncthreads();

    // ---- Pass C1: per-half exact (d2, j) bitonic-32 over <=24 candidates ----
    u64 arr[32];
#pragma unroll
    for (int u = 0; u < SLOT; ++u) {
        u32 jj = scomb[sb0 + u];
        if (jj != 0xFFFFFFFFu) {
            float d2 = dist2s(sx[jj], sy[jj], sz[jj], xi, yi, zi);
            arr[u] = ((u64)__float_as_uint(d2) << 32) | jj;
        } else {
            arr[u] = 0xFFFFFFFFFFFFFFFFull;
        }
    }
#pragma unroll
    for (int u = SLOT; u < 32; ++u) arr[u] = 0xFFFFFFFFFFFFFFFFull;

#pragma unroll
    for (int k = 2; k <= 32; k <<= 1) {
#pragma unroll
        for (int s = k >> 1; s > 0; s >>= 1) {
#pragma unroll
            for (int i = 0; i < 32; ++i) {
                int l = i ^ s;
                if (l > i) {
                    if ((i & k) == 0) ce64(arr[i], arr[l]);
                    else              ce64(arr[l], arr[i]);
                }
            }
        }
    }
    __syncthreads();   // slots consumed; scomb may be re-aliased

    // ---- Pass C2: half1 publishes sorted-16; half0 merges + writes out ----
    u64* sped = reinterpret_cast<u64*>(scomb);       // [64][16] u64 (fits 12 KB)
    if (half == 1) {
#pragma unroll
        for (int q = 0; q < KNN; ++q) sped[lp * KNN + q] = arr[q];
    }
    __syncthreads();
    if (half == 0) {
        u64 m[KNN];
#pragma unroll
        for (int i = 0; i < KNN; ++i) {
            u64 o = sped[lp * KNN + (KNN - 1 - i)];
            m[i] = (arr[i] < o) ? arr[i] : o;        // fold: lowest-16 of union
        }
#pragma unroll
        for (int s = 8; s > 0; s >>= 1) {            // bitonic clean
#pragma unroll
            for (int i = 0; i < KNN; ++i) {
                int l = i ^ s;
                if (l > i) ce64(m[i], m[l]);
            }
        }
        const int gi = base + li;
#pragma unroll
        for (int q = 0; q < KNN; ++q)
            idx_out[gi * KNN + q] = base + (int)(u32)(m[q] & 0xFFFFFFFFull);
    }
}

// ---------------------------------------------------------------------------
// Prep for layer 1 (h == p): S[j] = p_j@(Wh+Wr), R[i] = p_i@Wr
// ---------------------------------------------------------------------------
__global__ void prep1_kernel(const float* __restrict__ pos,
                             const float* __restrict__ w1a,
                             float* __restrict__ S, float* __restrict__ R) {
    int t = blockIdx.x * blockDim.x + threadIdx.x;
    int node = t >> 5;
    int c    = t & 31;
    float x = pos[node * 3 + 0];
    float y = pos[node * 3 + 1];
    float z = pos[node * 3 + 2];
    float wr0 = w1a[3 * 32 + c], wr1 = w1a[4 * 32 + c], wr2 = w1a[5 * 32 + c];
    float wh0 = w1a[0 * 32 + c] + wr0;
    float wh1 = w1a[1 * 32 + c] + wr1;
    float wh2 = w1a[2 * 32 + c] + wr2;
    S[t] = x * wh0 + y * wh1 + z * wh2;
    R[t] = x * wr0 + y * wr1 + z * wr2;
}

// ---------------------------------------------------------------------------
// Prep for layer 2: S[j] = h_j @ w2a[0:32] + p_j @ w2a[32:35]; R[i] = p_i @ Wr
// ---------------------------------------------------------------------------
__global__ void prep2_kernel(const float* __restrict__ pos,
                             const float* __restrict__ H,
                             const float* __restrict__ w2a,
                             float* __restrict__ S, float* __restrict__ R) {
    const int lane = threadIdx.x & 31;
    const int wid  = threadIdx.x >> 5;
    const int wpb  = blockDim.x >> 5;

    float wa[CH];
#pragma unroll
    for (int d = 0; d < CH; ++d) wa[d] = w2a[d * 32 + lane];
    const float wr0 = w2a[(32 + 0) * 32 + lane];
    const float wr1 = w2a[(32 + 1) * 32 + lane];
    const float wr2 = w2a[(32 + 2) * 32 + lane];

    for (int node = blockIdx.x * wpb + wid; node < NTOT; node += gridDim.x * wpb) {
        float x = pos[node * 3 + 0];
        float y = pos[node * 3 + 1];
        float z = pos[node * 3 + 2];
        float r = x * wr0 + y * wr1 + z * wr2;
        float h = H[node * 32 + lane];
        float acc = r;
#pragma unroll
        for (int d = 0; d < CH; ++d) {
            float hd = __shfl_sync(0xffffffffu, h, d);
            acc = fmaf(hd, wa[d], acc);
        }
        S[node * 32 + lane] = acc;
        R[node * 32 + lane] = r;
    }
}

// ---------------------------------------------------------------------------
// Edge MLP + max reduction. Warp per node; FFMA2 packed GEMV.
// ---------------------------------------------------------------------------
template <bool RELU_OUT>
__global__ void layer_kernel(const float* __restrict__ S,
                             const float* __restrict__ R,
                             const float* __restrict__ ba,
                             const float* __restrict__ wb,
                             const float* __restrict__ bb,
                             const int* __restrict__ idx,
                             float* __restrict__ out) {
    __shared__ __align__(16) float sE[8][KNN][CH];
    const int lane = threadIdx.x & 31;
    const int wid  = threadIdx.x >> 5;
    const int wpb  = blockDim.x >> 5;

    u64 wp[CH / 2];
#pragma unroll
    for (int d = 0; d < CH / 2; ++d)
        wp[d] = pack2(wb[(2 * d) * 32 + lane], wb[(2 * d + 1) * 32 + lane]);
    const float bav = ba[lane];
    const float bbv = bb[lane];

    for (int node = blockIdx.x * wpb + wid; node < NTOT; node += gridDim.x * wpb) {
        const float vb = bav - R[node * 32 + lane];
        const int myj  = idx[node * KNN + (lane & 15)];

#pragma unroll
        for (int k = 0; k < KNN; ++k) {
            int j = __shfl_sync(0xffffffffu, myj, k);
            float e = S[j * 32 + lane] + vb;
            sE[wid][k][lane] = fmaxf(e, 0.0f);
        }
        __syncwarp();

        float mx = -3.4e38f;
#pragma unroll
        for (int k = 0; k < KNN; ++k) {
            const ulonglong2* ek = reinterpret_cast<const ulonglong2*>(&sE[wid][k][0]);
            u64 a0 = 0, a1 = 0, a2 = 0, a3 = 0;
#pragma unroll
            for (int c = 0; c < 4; ++c) {
                ulonglong2 e2a = ek[2 * c + 0];
                ulonglong2 e2b = ek[2 * c + 1];
                a0 = ffma2(e2a.x, wp[4 * c + 0], a0);
                a1 = ffma2(e2a.y, wp[4 * c + 1], a1);
                a2 = ffma2(e2b.x, wp[4 * c + 2], a2);
                a3 = ffma2(e2b.y, wp[4 * c + 3], a3);
            }
            u64 t = fadd2(fadd2(a0, a1), fadd2(a2, a3));
            float lo, hi;
            unpack2(t, lo, hi);
            mx = fmaxf(mx, lo + hi);
        }
        __syncwarp();

        float r = mx + bbv;
        if (RELU_OUT) r = fmaxf(r, 0.0f);
        out[node * 32 + lane] = r;
    }
}

// ---------------------------------------------------------------------------
extern "C" void kernel_launch(void* const* d_in, const int* in_sizes, int n_in,
                              void* d_out, int out_size) {
    const float* pos = (const float*)d_in[0];
    const float* w1a = (const float*)d_in[2];
    const float* b1a = (const float*)d_in[3];
    const float* w1b = (const float*)d_in[4];
    const float* b1b = (const float*)d_in[5];
    const float* w2a = (const float*)d_in[6];
    const float* b2a = (const float*)d_in[7];
    const float* w2b = (const float*)d_in[8];
    const float* b2b = (const float*)d_in[9];
    float* out = (float*)d_out;

    int*   idx; cudaGetSymbolAddress((void**)&idx, g_idx);
    float* S;   cudaGetSymbolAddress((void**)&S,   g_S);
    float* R;   cudaGetSymbolAddress((void**)&R,   g_R);
    float* H;   cudaGetSymbolAddress((void**)&H,   g_H);

    // 1. kNN graph (1024 blocks: 32 batches x 32 point-chunks, 2 halves/point)
    knn_kernel<<<NB * 32, 128>>>(pos, idx);

    // 2. conv1
    prep1_kernel<<<(NTOT * CH) / 256, 256>>>(pos, w1a, S, R);
    layer_kernel<true><<<1024, 256>>>(S, R, b1a, w1b, b1b, idx, H);

    // 3. conv2
    prep2_kernel<<<1024, 256>>>(pos, H, w2a, S, R);
    layer_kernel<false><<<1024, 256>>>(S, R, b2a, w2b, b2b, idx, out);
}

// round 7
// speedup vs baseline: 2.1898x; 1.1704x over previous
#include <cuda_runtime.h>
#include <cuda_fp16.h>
#include <cstdint>

#define NB    32
#define NPTS  2048
#define KNN   16
#define NTOT  (NB * NPTS)
#define CH    32
#define HALF  1024           // candidates per half
#define PPB   64             // points per block (x2 halves = 128 threads)
#define SLOT  32             // candidate slots per (point, half)

// Scratch (device globals: no allocation allowed in kernel_launch)
__device__ int   g_idx[NTOT * KNN];
__device__ float g_S[NTOT * CH];
__device__ float g_R[NTOT * CH];
__device__ float g_H[NTOT * CH];

typedef unsigned long long u64;
typedef unsigned int u32;

// ---------------------------------------------------------------------------
// packed f32x2 helpers (layer kernel)
// ---------------------------------------------------------------------------
__device__ __forceinline__ u64 ffma2(u64 a, u64 b, u64 c) {
    u64 d; asm("fma.rn.f32x2 %0, %1, %2, %3;" : "=l"(d) : "l"(a), "l"(b), "l"(c)); return d;
}
__device__ __forceinline__ u64 fadd2(u64 a, u64 b) {
    u64 d; asm("add.rn.f32x2 %0, %1, %2;" : "=l"(d) : "l"(a), "l"(b)); return d;
}
__device__ __forceinline__ u64 pack2(float lo, float hi) {
    u64 d; asm("mov.b64 %0, {%1, %2};" : "=l"(d) : "f"(lo), "f"(hi)); return d;
}
__device__ __forceinline__ void unpack2(u64 v, float& lo, float& hi) {
    asm("mov.b64 {%0, %1}, %2;" : "=f"(lo), "=f"(hi) : "l"(v));
}

// ---------------------------------------------------------------------------
// compare-exchange helpers
// ---------------------------------------------------------------------------
__device__ __forceinline__ void ce2h(__half2& a, __half2& b) {   // packed f16 CE
    __half2 lo = __hmin2(a, b), hi = __hmax2(a, b);
    a = lo; b = hi;
}
__device__ __forceinline__ void ce_f(float& a, float& b) {
    float lo = fminf(a, b), hi = fmaxf(a, b);
    a = lo; b = hi;
}
__device__ __forceinline__ void ce64(u64& a, u64& b) {
    u64 x = a, y = b;
    bool sw = (y < x);
    a = sw ? y : x;
    b = sw ? x : y;
}
__device__ __forceinline__ __half2 h2(u32 v) {
    return *reinterpret_cast<const __half2*>(&v);
}
__device__ __forceinline__ float dist2s(float x, float y, float z,
                                        float xi, float yi, float zi) {
    float dx = x - xi, dy = y - yi, dz = z - zi;
    return fmaf(dz, dz, fmaf(dy, dy, dx * dx));
}

// ---------------------------------------------------------------------------
// kNN. Block = 64 points x 2 candidate-halves (128 threads).
// Keys: f16 shifted dot-product key(j) = |p_j|^2 - 2 p_j . p_i (monotone in d2
// up to bounded f16 error M). Pass A keeps 8 streams x top-4 per thread
// (truncation keeps kappa a valid upper bound). Collect bound T = kappa + 2M.
// Pass C re-sorts collected candidates by EXACT f32 (d2, j) -> exact top-16
// with low-index tie-break, matching jax.lax.top_k.
// ---------------------------------------------------------------------------
__global__ void knn_kernel(const float* __restrict__ pos, int* __restrict__ idx_out) {
    __shared__ __align__(16) __half shx[NPTS], shy[NPTS], shz[NPTS], shw[NPTS]; // 16KB
    __shared__ __align__(16) u32 sbuf[128 * 33];                                // 16.9KB

    const int b     = blockIdx.x >> 5;          // 32 blocks of 64 points per batch
    const int chunk = blockIdx.x & 31;
    const int base  = b * NPTS;
    const int tid   = threadIdx.x;
    const int half  = tid >> 6;                 // 0 or 1
    const int lp    = tid & 63;                 // local point 0..63
    const int li    = chunk * PPB + lp;
    const int j0    = half * HALF;

    for (int t = tid; t < NPTS; t += 128) {
        const float* p = pos + (base + t) * 3;
        float x = p[0], y = p[1], z = p[2];
        shx[t] = __float2half_rn(x);
        shy[t] = __float2half_rn(y);
        shz[t] = __float2half_rn(z);
        shw[t] = __float2half_rn(x * x + y * y + z * z);
    }
    const float xi = pos[(base + li) * 3 + 0];
    const float yi = pos[(base + li) * 3 + 1];
    const float zi = pos[(base + li) * 3 + 2];
    __syncthreads();

    // -2 * f16(coord) is exact in f16
    const __half mtwo = __float2half_rn(-2.0f);
    const __half2 m2x = __half2half2(__hmul(__float2half_rn(xi), mtwo));
    const __half2 m2y = __half2half2(__hmul(__float2half_rn(yi), mtwo));
    const __half2 m2z = __half2half2(__hmul(__float2half_rn(zi), mtwo));

    const __half2 HINF2 = __half2half2(__ushort_as_half(0x7C00));
    __half2 best[4][4];                         // 4 bundles x depth 4 (=8 streams)
#pragma unroll
    for (int g = 0; g < 4; ++g)
#pragma unroll
        for (int d = 0; d < 4; ++d) best[g][d] = HINF2;

    // ---- Pass A: 8-stream x top-4 streaming over this half ----
#pragma unroll 1
    for (int tile = 0; tile < HALF / 32; ++tile) {
        const int jb = j0 + tile * 32;
#pragma unroll
        for (int g = 0; g < 4; ++g) {
            const int o = jb + 8 * g;
            uint4 xv = *reinterpret_cast<const uint4*>(&shx[o]);
            uint4 yv = *reinterpret_cast<const uint4*>(&shy[o]);
            uint4 zv = *reinterpret_cast<const uint4*>(&shz[o]);
            uint4 wv = *reinterpret_cast<const uint4*>(&shw[o]);
            __half2 k0 = __hfma2(h2(zv.x), m2z, __hfma2(h2(yv.x), m2y, __hfma2(h2(xv.x), m2x, h2(wv.x))));
            __half2 k1 = __hfma2(h2(zv.y), m2z, __hfma2(h2(yv.y), m2y, __hfma2(h2(xv.y), m2x, h2(wv.y))));
            __half2 k2 = __hfma2(h2(zv.z), m2z, __hfma2(h2(yv.z), m2y, __hfma2(h2(xv.z), m2x, h2(wv.z))));
            __half2 k3 = __hfma2(h2(zv.w), m2z, __hfma2(h2(yv.w), m2y, __hfma2(h2(xv.w), m2x, h2(wv.w))));
            // bitonic sort-4 ascending (both packed streams)
            ce2h(k0, k1); ce2h(k3, k2);
            ce2h(k0, k2); ce2h(k1, k3);
            ce2h(k0, k1); ce2h(k2, k3);
            // fold lowest-4 into sorted best
            best[g][0] = __hmin2(best[g][0], k3);
            best[g][1] = __hmin2(best[g][1], k2);
            best[g][2] = __hmin2(best[g][2], k1);
            best[g][3] = __hmin2(best[g][3], k0);
            // bitonic clean-4
            ce2h(best[g][0], best[g][2]); ce2h(best[g][1], best[g][3]);
            ce2h(best[g][0], best[g][1]); ce2h(best[g][2], best[g][3]);
        }
    }

    // ---- per-thread merge: sort the 32 kept values, keep lowest 16 ----
    float v[32];
#pragma unroll
    for (int g = 0; g < 4; ++g)
#pragma unroll
        for (int d = 0; d < 4; ++d) {
            v[g * 8 + d]     = __low2float(best[g][d]);
            v[g * 8 + 4 + d] = __high2float(best[g][d]);
        }
#pragma unroll
    for (int k = 2; k <= 32; k <<= 1) {
#pragma unroll
        for (int s = k >> 1; s > 0; s >>= 1) {
#pragma unroll
            for (int i = 0; i < 32; ++i) {
                int l = i ^ s;
                if (l > i) {
                    if ((i & k) == 0) ce_f(v[i], v[l]);
                    else              ce_f(v[l], v[i]);
                }
            }
        }
    }

    // publish sorted-16; kappa = 16th of the 2-thread union (fold identity)
    float* skap = reinterpret_cast<float*>(sbuf);       // [128] stride 17
#pragma unroll
    for (int q = 0; q < KNN; ++q) skap[tid * 17 + q] = v[q];
    __syncthreads();

    float kap = -3.4e38f;
#pragma unroll
    for (int i = 0; i < KNN; ++i)
        kap = fmaxf(kap, fminf(skap[lp * 17 + i], skap[(lp + 64) * 17 + (KNN - 1 - i)]));

    // margin for f16 key error (cancellation-aware, per-point)
    const float r  = sqrtf(xi * xi + yi * yi + zi * zi);
    const float M  = 0.003f * (r + 1.6f) * (3.0f * r + 1.6f);
    const float T  = kap + 2.0f * M + 1e-3f;
    const __half2 T2 = __half2half2(__float2half_ru(T));
    __syncthreads();

    // reinit sbuf as candidate slots [128][33]
#pragma unroll
    for (int u = 0; u < SLOT; ++u) sbuf[tid * 33 + u] = 0xFFFFFFFFu;
    __syncthreads();

    // ---- Pass B: collect candidates with key <= T from this half ----
    int cnt = 0;
    const int sb0 = tid * 33;
#pragma unroll 2
    for (int o = j0; o < j0 + HALF; o += 8) {
        uint4 xv = *reinterpret_cast<const uint4*>(&shx[o]);
        uint4 yv = *reinterpret_cast<const uint4*>(&shy[o]);
        uint4 zv = *reinterpret_cast<const uint4*>(&shz[o]);
        uint4 wv = *reinterpret_cast<const uint4*>(&shw[o]);
        __half2 k0 = __hfma2(h2(zv.x), m2z, __hfma2(h2(yv.x), m2y, __hfma2(h2(xv.x), m2x, h2(wv.x))));
        __half2 k1 = __hfma2(h2(zv.y), m2z, __hfma2(h2(yv.y), m2y, __hfma2(h2(xv.y), m2x, h2(wv.y))));
        __half2 k2 = __hfma2(h2(zv.z), m2z, __hfma2(h2(yv.z), m2y, __hfma2(h2(xv.z), m2x, h2(wv.z))));
        __half2 k3 = __hfma2(h2(zv.w), m2z, __hfma2(h2(yv.w), m2y, __hfma2(h2(xv.w), m2x, h2(wv.w))));
        u32 m0 = __hle2_mask(k0, T2);
        u32 m1 = __hle2_mask(k1, T2);
        u32 m2 = __hle2_mask(k2, T2);
        u32 m3 = __hle2_mask(k3, T2);
        if ((m0 | m1 | m2 | m3) == 0u) continue;
        if (m0 & 0x0000FFFFu) { if (cnt < SLOT) sbuf[sb0 + cnt++] = (u32)(o + 0); }
        if (m0 & 0xFFFF0000u) { if (cnt < SLOT) sbuf[sb0 + cnt++] = (u32)(o + 1); }
        if (m1 & 0x0000FFFFu) { if (cnt < SLOT) sbuf[sb0 + cnt++] = (u32)(o + 2); }
        if (m1 & 0xFFFF0000u) { if (cnt < SLOT) sbuf[sb0 + cnt++] = (u32)(o + 3); }
        if (m2 & 0x0000FFFFu) { if (cnt < SLOT) sbuf[sb0 + cnt++] = (u32)(o + 4); }
        if (m2 & 0xFFFF0000u) { if (cnt < SLOT) sbuf[sb0 + cnt++] = (u32)(o + 5); }
        if (m3 & 0x0000FFFFu) { if (cnt < SLOT) sbuf[sb0 + cnt++] = (u32)(o + 6); }
        if (m3 & 0xFFFF0000u) { if (cnt < SLOT) sbuf[sb0 + cnt++] = (u32)(o + 7); }
    }

    // ---- Pass C: exact f32 (d2, j) selection over own slots ----
    u64 arr[32];
#pragma unroll
    for (int u = 0; u < SLOT; ++u) {
        u32 jj = sbuf[sb0 + u];
        u64 key = 0xFFFFFFFFFFFFFFFFull;
        if (jj != 0xFFFFFFFFu) {
            const float* pj = pos + (base + (int)jj) * 3;
            float d2 = dist2s(pj[0], pj[1], pj[2], xi, yi, zi);
            key = ((u64)__float_as_uint(d2) << 32) | jj;
        }
        arr[u] = key;
    }
#pragma unroll
    for (int k = 2; k <= 32; k <<= 1) {
#pragma unroll
        for (int s = k >> 1; s > 0; s >>= 1) {
#pragma unroll
            for (int i = 0; i < 32; ++i) {
                int l = i ^ s;
                if (l > i) {
                    if ((i & k) == 0) ce64(arr[i], arr[l]);
                    else              ce64(arr[l], arr[i]);
                }
            }
        }
    }
    __syncthreads();   // all slot reads done; sbuf may be re-aliased

    // ---- merge halves: half1 publishes sorted-16; half0 folds + writes ----
    u64* sped = reinterpret_cast<u64*>(sbuf);          // [64] stride 17 u64
    if (half == 1) {
#pragma unroll
        for (int q = 0; q < KNN; ++q) sped[lp * 17 + q] = arr[q];
    }
    __syncthreads();
    if (half == 0) {
        u64 m[KNN];
#pragma unroll
        for (int i = 0; i < KNN; ++i) {
            u64 o = sped[lp * 17 + (KNN - 1 - i)];
            m[i] = (arr[i] < o) ? arr[i] : o;
        }
#pragma unroll
        for (int s = 8; s > 0; s >>= 1) {
#pragma unroll
            for (int i = 0; i < KNN; ++i) {
                int l = i ^ s;
                if (l > i) ce64(m[i], m[l]);
            }
        }
        const int gi = base + li;
#pragma unroll
        for (int q = 0; q < KNN; ++q)
            idx_out[gi * KNN + q] = base + (int)(u32)(m[q] & 0xFFFFFFFFull);
    }
}

// ---------------------------------------------------------------------------
// Prep for layer 1 (h == p): S[j] = p_j@(Wh+Wr), R[i] = p_i@Wr
// ---------------------------------------------------------------------------
__global__ void prep1_kernel(const float* __restrict__ pos,
                             const float* __restrict__ w1a,
                             float* __restrict__ S, float* __restrict__ R) {
    int t = blockIdx.x * blockDim.x + threadIdx.x;
    int node = t >> 5;
    int c    = t & 31;
    float x = pos[node * 3 + 0];
    float y = pos[node * 3 + 1];
    float z = pos[node * 3 + 2];
    float wr0 = w1a[3 * 32 + c], wr1 = w1a[4 * 32 + c], wr2 = w1a[5 * 32 + c];
    float wh0 = w1a[0 * 32 + c] + wr0;
    float wh1 = w1a[1 * 32 + c] + wr1;
    float wh2 = w1a[2 * 32 + c] + wr2;
    S[t] = x * wh0 + y * wh1 + z * wh2;
    R[t] = x * wr0 + y * wr1 + z * wr2;
}

// ---------------------------------------------------------------------------
// Prep for layer 2: S[j] = h_j @ w2a[0:32] + p_j @ w2a[32:35]; R[i] = p_i @ Wr
// ---------------------------------------------------------------------------
__global__ void prep2_kernel(const float* __restrict__ pos,
                             const float* __restrict__ H,
                             const float* __restrict__ w2a,
                             float* __restrict__ S, float* __restrict__ R) {
    const int lane = threadIdx.x & 31;
    const int wid  = threadIdx.x >> 5;
    const int wpb  = blockDim.x >> 5;

    float wa[CH];
#pragma unroll
    for (int d = 0; d < CH; ++d) wa[d] = w2a[d * 32 + lane];
    const float wr0 = w2a[(32 + 0) * 32 + lane];
    const float wr1 = w2a[(32 + 1) * 32 + lane];
    const float wr2 = w2a[(32 + 2) * 32 + lane];

    for (int node = blockIdx.x * wpb + wid; node < NTOT; node += gridDim.x * wpb) {
        float x = pos[node * 3 + 0];
        float y = pos[node * 3 + 1];
        float z = pos[node * 3 + 2];
        float r = x * wr0 + y * wr1 + z * wr2;
        float h = H[node * 32 + lane];
        float acc = r;
#pragma unroll
        for (int d = 0; d < CH; ++d) {
            float hd = __shfl_sync(0xffffffffu, h, d);
            acc = fmaf(hd, wa[d], acc);
        }
        S[node * 32 + lane] = acc;
        R[node * 32 + lane] = r;
    }
}

// ---------------------------------------------------------------------------
// Edge MLP + max reduction. Warp per node; FFMA2 packed GEMV.
// ---------------------------------------------------------------------------
template <bool RELU_OUT>
__global__ void layer_kernel(const float* __restrict__ S,
                             const float* __restrict__ R,
                             const float* __restrict__ ba,
                             const float* __restrict__ wb,
                             const float* __restrict__ bb,
                             const int* __restrict__ idx,
                             float* __restrict__ out) {
    __shared__ __align__(16) float sE[8][KNN][CH];
    const int lane = threadIdx.x & 31;
    const int wid  = threadIdx.x >> 5;
    const int wpb  = blockDim.x >> 5;

    u64 wp[CH / 2];
#pragma unroll
    for (int d = 0; d < CH / 2; ++d)
        wp[d] = pack2(wb[(2 * d) * 32 + lane], wb[(2 * d + 1) * 32 + lane]);
    const float bav = ba[lane];
    const float bbv = bb[lane];

    for (int node = blockIdx.x * wpb + wid; node < NTOT; node += gridDim.x * wpb) {
        const float vb = bav - R[node * 32 + lane];
        const int myj  = idx[node * KNN + (lane & 15)];

#pragma unroll
        for (int k = 0; k < KNN; ++k) {
            int j = __shfl_sync(0xffffffffu, myj, k);
            float e = S[j * 32 + lane] + vb;
            sE[wid][k][lane] = fmaxf(e, 0.0f);
        }
        __syncwarp();

        float mx = -3.4e38f;
#pragma unroll
        for (int k = 0; k < KNN; ++k) {
            const ulonglong2* ek = reinterpret_cast<const ulonglong2*>(&sE[wid][k][0]);
            u64 a0 = 0, a1 = 0, a2 = 0, a3 = 0;
#pragma unroll
            for (int c = 0; c < 4; ++c) {
                ulonglong2 e2a = ek[2 * c + 0];
                ulonglong2 e2b = ek[2 * c + 1];
                a0 = ffma2(e2a.x, wp[4 * c + 0], a0);
                a1 = ffma2(e2a.y, wp[4 * c + 1], a1);
                a2 = ffma2(e2b.x, wp[4 * c + 2], a2);
                a3 = ffma2(e2b.y, wp[4 * c + 3], a3);
            }
            u64 t = fadd2(fadd2(a0, a1), fadd2(a2, a3));
            float lo, hi;
            unpack2(t, lo, hi);
            mx = fmaxf(mx, lo + hi);
        }
        __syncwarp();

        float r = mx + bbv;
        if (RELU_OUT) r = fmaxf(r, 0.0f);
        out[node * 32 + lane] = r;
    }
}

// ---------------------------------------------------------------------------
extern "C" void kernel_launch(void* const* d_in, const int* in_sizes, int n_in,
                              void* d_out, int out_size) {
    const float* pos = (const float*)d_in[0];
    const float* w1a = (const float*)d_in[2];
    const float* b1a = (const float*)d_in[3];
    const float* w1b = (const float*)d_in[4];
    const float* b1b = (const float*)d_in[5];
    const float* w2a = (const float*)d_in[6];
    const float* b2a = (const float*)d_in[7];
    const float* w2b = (const float*)d_in[8];
    const float* b2b = (const float*)d_in[9];
    float* out = (float*)d_out;

    int*   idx; cudaGetSymbolAddress((void**)&idx, g_idx);
    float* S;   cudaGetSymbolAddress((void**)&S,   g_S);
    float* R;   cudaGetSymbolAddress((void**)&R,   g_R);
    float* H;   cudaGetSymbolAddress((void**)&H,   g_H);

    // 1. kNN graph
    knn_kernel<<<NB * 32, 128>>>(pos, idx);

    // 2. conv1
    prep1_kernel<<<(NTOT * CH) / 256, 256>>>(pos, w1a, S, R);
    layer_kernel<true><<<1024, 256>>>(S, R, b1a, w1b, b1b, idx, H);

    // 3. conv2
    prep2_kernel<<<1024, 256>>>(pos, H, w2a, S, R);
    layer_kernel<false><<<1024, 256>>>(S, R, b2a, w2b, b2b, idx, out);
}